// round 1
// baseline (speedup 1.0000x reference)
#include <cuda_runtime.h>
#include <math.h>

#define D 128
#define WIN 128
#define BATCH 8
#define SEQ 8192
#define STR 132                       // smem row stride (floats), 16B-aligned
#define SMEM_BYTES (3 * 128 * STR * 4)

// Fused weight products (computed once per launch by precompute_kernel)
__device__ float g_MT[D * D];  // g_MT[j][d] = M[d][j],  M = Wq @ Wk^T
__device__ float g_NT[D * D];  // g_NT[j][d] = N[d][j],  N = Wv @ Wo

// ---------------------------------------------------------------------------
// Precompute MT/NT: grid=128 (d), block=128 (t)
// ---------------------------------------------------------------------------
__global__ void precompute_kernel(const float* __restrict__ Wq,
                                  const float* __restrict__ Wk,
                                  const float* __restrict__ Wv,
                                  const float* __restrict__ Wo) {
    __shared__ float wk[D], wv[D];
    int d = blockIdx.x;
    int t = threadIdx.x;
    wk[t] = Wk[d * D + t];
    wv[t] = Wv[d * D + t];
    __syncthreads();
    // g_MT[d][t] = sum_f Wk[d][f] * Wq[t][f]  ( = M[t][d] with M = Wq Wk^T )
    float acc = 0.f;
    #pragma unroll 4
    for (int f = 0; f < D; f++) acc += wk[f] * Wq[t * D + f];
    g_MT[d * D + t] = acc;
    // g_NT[t][d] = sum_f Wv[d][f] * Wo[f][t]  ( = N[d][t] with N = Wv Wo )
    float acc2 = 0.f;
    #pragma unroll 4
    for (int f = 0; f < D; f++) acc2 += wv[f] * Wo[f * D + t];
    g_NT[t * D + d] = acc2;
}

// ---------------------------------------------------------------------------
// Fill second half of output with gelu(beta[c]) (zero-padded half is constant)
// ---------------------------------------------------------------------------
__global__ void fill_kernel(const float* __restrict__ beta,
                            float4* __restrict__ out4) {
    __shared__ float gb[D];
    int t = threadIdx.x;
    if (t < D) {
        float b = beta[t];
        gb[t] = 0.5f * b * (1.f + erff(b * 0.70710678118654752f));
    }
    __syncthreads();
    const int n4 = BATCH * SEQ * (D / 4);  // second-half float4 count
    for (int i = blockIdx.x * blockDim.x + t; i < n4;
         i += gridDim.x * blockDim.x) {
        int row = i >> 5;          // / (D/4)
        int c4  = i & 31;
        int b   = row / SEQ;
        int s   = row - b * SEQ;
        float4 v = make_float4(gb[c4 * 4], gb[c4 * 4 + 1],
                               gb[c4 * 4 + 2], gb[c4 * 4 + 3]);
        out4[(b * 2 * SEQ + SEQ + s) * (D / 4) + c4] = v;
    }
}

// ---------------------------------------------------------------------------
// acc[r][c] = sum_d A[i][d] * B[j][d],  i = ty+16r, j = tx+16c  (A * B^T)
// ---------------------------------------------------------------------------
__device__ __forceinline__ void gemm_ab(const float* __restrict__ A,
                                        const float* __restrict__ Bm,
                                        int ty, int tx, float acc[8][8]) {
    #pragma unroll
    for (int r = 0; r < 8; r++)
        #pragma unroll
        for (int c = 0; c < 8; c++) acc[r][c] = 0.f;

    #pragma unroll 1
    for (int d = 0; d < D; d += 4) {
        float4 a[8], bb[8];
        #pragma unroll
        for (int r = 0; r < 8; r++)
            a[r] = *(const float4*)&A[(ty + 16 * r) * STR + d];
        #pragma unroll
        for (int c = 0; c < 8; c++)
            bb[c] = *(const float4*)&Bm[(tx + 16 * c) * STR + d];
        #pragma unroll
        for (int r = 0; r < 8; r++)
            #pragma unroll
            for (int c = 0; c < 8; c++) {
                acc[r][c] += a[r].x * bb[c].x;
                acc[r][c] += a[r].y * bb[c].y;
                acc[r][c] += a[r].z * bb[c].z;
                acc[r][c] += a[r].w * bb[c].w;
            }
    }
}

// ---------------------------------------------------------------------------
// Main: one CTA per (batch, block). 256 threads, 8x8 register tiles.
// ---------------------------------------------------------------------------
__global__ void __launch_bounds__(256, 1)
attn_kernel(const float* __restrict__ x,
            const float* __restrict__ gamma,
            const float* __restrict__ beta,
            float* __restrict__ out) {
    extern __shared__ float smem[];
    float* sX = smem;                  // X block, later U^T
    float* sA = smem + 128 * STR;      // T, later P
    float* sB = smem + 2 * 128 * STR;  // MT, later NT

    int tid = threadIdx.x;
    int tx = tid & 15, ty = tid >> 4;
    int blk = blockIdx.x;              // 0..511
    int b = blk >> 6, n = blk & 63;
    const float* Xg = x + (b * SEQ + n * WIN) * D;

    // Load X and MT (coalesced float4)
    for (int i = tid; i < 128 * 32; i += 256) {
        int r = i >> 5, c = i & 31;
        *(float4*)&sX[r * STR + c * 4] = ((const float4*)Xg)[i];
        *(float4*)&sB[r * STR + c * 4] = ((const float4*)g_MT)[i];
    }
    __syncthreads();

    float acc[8][8];

    // GEMM1: T = X * M   (acc = sX * sB^T)
    gemm_ab(sX, sB, ty, tx, acc);
    __syncthreads();
    #pragma unroll
    for (int r = 0; r < 8; r++)
        #pragma unroll
        for (int c = 0; c < 8; c++)
            sA[(ty + 16 * r) * STR + tx + 16 * c] = acc[r][c];
    __syncthreads();

    // GEMM2: S = T * X^T, scale, softmax -> P (in registers)
    gemm_ab(sA, sX, ty, tx, acc);
    const float scale = 0.08838834764831845f;  // 1/sqrt(128)
    #pragma unroll
    for (int r = 0; r < 8; r++) {
        float m = -1e30f;
        #pragma unroll
        for (int c = 0; c < 8; c++) {
            acc[r][c] *= scale;
            m = fmaxf(m, acc[r][c]);
        }
        #pragma unroll
        for (int off = 8; off; off >>= 1)
            m = fmaxf(m, __shfl_xor_sync(0xffffffffu, m, off, 16));
        float s = 0.f;
        #pragma unroll
        for (int c = 0; c < 8; c++) {
            acc[r][c] = __expf(acc[r][c] - m);
            s += acc[r][c];
        }
        #pragma unroll
        for (int off = 8; off; off >>= 1)
            s += __shfl_xor_sync(0xffffffffu, s, off, 16);
        float inv = 1.0f / s;
        #pragma unroll
        for (int c = 0; c < 8; c++) acc[r][c] *= inv;
    }
    __syncthreads();  // all GEMM2 reads of sA done
    // P -> sA; NT -> sB (MT dead)
    #pragma unroll
    for (int r = 0; r < 8; r++)
        #pragma unroll
        for (int c = 0; c < 8; c++)
            sA[(ty + 16 * r) * STR + tx + 16 * c] = acc[r][c];
    for (int i = tid; i < 128 * 32; i += 256) {
        int r = i >> 5, c = i & 31;
        *(float4*)&sB[r * STR + c * 4] = ((const float4*)g_NT)[i];
    }
    __syncthreads();

    // GEMM3: U = X * N   (acc = sX * sB^T)
    gemm_ab(sX, sB, ty, tx, acc);
    __syncthreads();  // all GEMM3 reads of sX done
    // Store U transposed into sX: UT[j][k] = U[k][j]
    #pragma unroll
    for (int r = 0; r < 8; r++)
        #pragma unroll
        for (int c = 0; c < 8; c++)
            sX[(tx + 16 * c) * STR + (ty + 16 * r)] = acc[r][c];
    __syncthreads();

    // GEMM4: H = P * U   (acc = sA * (U^T)^T)
    gemm_ab(sA, sX, ty, tx, acc);

    // LayerNorm (row-wise over 128) + exact GELU + store
    float* outp = out + (b * 2 * SEQ + n * WIN) * D;
    float gcol[8], bcol[8];
    #pragma unroll
    for (int c = 0; c < 8; c++) {
        gcol[c] = gamma[tx + 16 * c];
        bcol[c] = beta[tx + 16 * c];
    }
    #pragma unroll
    for (int r = 0; r < 8; r++) {
        float s = 0.f;
        #pragma unroll
        for (int c = 0; c < 8; c++) s += acc[r][c];
        #pragma unroll
        for (int off = 8; off; off >>= 1)
            s += __shfl_xor_sync(0xffffffffu, s, off, 16);
        float mu = s * (1.0f / 128.0f);
        float v = 0.f;
        #pragma unroll
        for (int c = 0; c < 8; c++) {
            float dlt = acc[r][c] - mu;
            v += dlt * dlt;
        }
        #pragma unroll
        for (int off = 8; off; off >>= 1)
            v += __shfl_xor_sync(0xffffffffu, v, off, 16);
        float rstd = rsqrtf(v * (1.0f / 128.0f) + 1e-5f);
        int row = ty + 16 * r;
        #pragma unroll
        for (int c = 0; c < 8; c++) {
            float y = (acc[r][c] - mu) * rstd * gcol[c] + bcol[c];
            float g = 0.5f * y * (1.f + erff(y * 0.70710678118654752f));
            outp[row * D + tx + 16 * c] = g;
        }
    }
}

// ---------------------------------------------------------------------------
extern "C" void kernel_launch(void* const* d_in, const int* in_sizes, int n_in,
                              void* d_out, int out_size) {
    const float* x     = (const float*)d_in[0];
    const float* Wq    = (const float*)d_in[1];
    const float* Wk    = (const float*)d_in[2];
    const float* Wv    = (const float*)d_in[3];
    const float* Wo    = (const float*)d_in[4];
    const float* gamma = (const float*)d_in[5];
    const float* beta  = (const float*)d_in[6];
    float* out = (float*)d_out;

    cudaFuncSetAttribute(attn_kernel,
                         cudaFuncAttributeMaxDynamicSharedMemorySize,
                         SMEM_BYTES);

    precompute_kernel<<<128, 128>>>(Wq, Wk, Wv, Wo);
    fill_kernel<<<1024, 256>>>(beta, (float4*)out);
    attn_kernel<<<BATCH * (SEQ / WIN), 256, SMEM_BYTES>>>(x, gamma, beta, out);
}

// round 4
// speedup vs baseline: 1.6273x; 1.6273x over previous
#include <cuda_runtime.h>
#include <math.h>

#define D 128
#define WIN 128
#define BATCH 8
#define SEQ 8192
#define STR 132                        // smem row stride in floats (k-major rows)
#define SMEM_BYTES (3 * 128 * STR * 4) // 3 buffers of 128 x STR floats = 198 KB
#define SCALE 0.08838834764831845f     // 1/sqrt(128)

typedef unsigned long long ull;

// Fused weights, row-major [d][j]:  g_M = (Wq Wk^T)*SCALE,  g_N = Wv Wo
__device__ float g_M[D * D];
__device__ float g_N[D * D];

// ---------------- f32x2 helpers ----------------
__device__ __forceinline__ ull pk(float x, float y) {
    ull r;
    asm("mov.b64 %0, {%1, %2};" : "=l"(r) : "f"(x), "f"(y));
    return r;
}
__device__ __forceinline__ void upk(ull v, float& x, float& y) {
    asm("mov.b64 {%0, %1}, %2;" : "=f"(x), "=f"(y) : "l"(v));
}
__device__ __forceinline__ void fma2(ull& d, ull a, ull b) {
    asm("fma.rn.f32x2 %0, %1, %2, %0;" : "+l"(d) : "l"(a), "l"(b));
}

__device__ __forceinline__ float rmax16(float v) {
    #pragma unroll
    for (int off = 8; off; off >>= 1)
        v = fmaxf(v, __shfl_xor_sync(0xffffffffu, v, off, 16));
    return v;
}
__device__ __forceinline__ float rsum16(float v) {
    #pragma unroll
    for (int off = 8; off; off >>= 1)
        v += __shfl_xor_sync(0xffffffffu, v, off, 16);
    return v;
}

// ---------------------------------------------------------------------------
// Precompute fused weights. grid=128 (d), block=128 (t).
//   g_M[d][t] = SCALE * sum_f Wq[d][f] * Wk[t][f]
//   g_N[d][t] =         sum_f Wv[d][f] * Wo[f][t]
// ---------------------------------------------------------------------------
__global__ void __launch_bounds__(128, 8)
precompute_kernel(const float* __restrict__ Wq, const float* __restrict__ Wk,
                  const float* __restrict__ Wv, const float* __restrict__ Wo) {
    __shared__ float wq[D], wv[D];
    int d = blockIdx.x, t = threadIdx.x;
    wq[t] = Wq[d * D + t];
    wv[t] = Wv[d * D + t];
    __syncthreads();

    float aM = 0.f;
    const float4* Wk4 = (const float4*)(Wk + t * D);
    #pragma unroll 8
    for (int f4 = 0; f4 < 32; f4++) {
        float4 k4 = __ldg(&Wk4[f4]);
        aM += wq[f4 * 4 + 0] * k4.x + wq[f4 * 4 + 1] * k4.y +
              wq[f4 * 4 + 2] * k4.z + wq[f4 * 4 + 3] * k4.w;
    }
    float aN = 0.f;
    #pragma unroll 8
    for (int f = 0; f < D; f++) aN += wv[f] * __ldg(&Wo[f * D + t]);

    g_M[d * D + t] = aM * SCALE;
    g_N[d * D + t] = aN;
}

// ---------------------------------------------------------------------------
// Fill second (zero-padded) half of output with gelu(beta[c])
// ---------------------------------------------------------------------------
__global__ void fill_kernel(const float* __restrict__ beta,
                            float4* __restrict__ out4) {
    __shared__ float gb[D];
    int t = threadIdx.x;
    if (t < D) {
        float b = beta[t];
        gb[t] = 0.5f * b * (1.f + erff(b * 0.70710678118654752f));
    }
    __syncthreads();
    const int n4 = BATCH * SEQ * (D / 4);
    for (int i = blockIdx.x * blockDim.x + t; i < n4;
         i += gridDim.x * blockDim.x) {
        int row = i >> 5;
        int c4 = i & 31;
        int b = row / SEQ;
        int s = row - b * SEQ;
        float4 v = make_float4(gb[c4 * 4], gb[c4 * 4 + 1], gb[c4 * 4 + 2],
                               gb[c4 * 4 + 3]);
        out4[(b * 2 * SEQ + SEQ + s) * (D / 4) + c4] = v;
    }
}

// ---------------------------------------------------------------------------
// 8x8 register-tile GEMM over k-major operands:
//   acc pair p of row r covers cols (j0+2p, j0+2p+1):
//   acc[r][p] += A[k][i0+r] * (B[k][j0+2p], B[k][j0+2p+1])
// All loads: k fixed warp-wide, lanes at 32B stride -> conflict-free.
// ---------------------------------------------------------------------------
__device__ __forceinline__ void gemm8x8(const float* __restrict__ A,
                                        const float* __restrict__ B,
                                        int i0, int j0, ull acc[32]) {
    #pragma unroll
    for (int q = 0; q < 32; q++) acc[q] = 0ull;

    #pragma unroll 2
    for (int k = 0; k < D; k++) {
        const float* ar = A + k * STR + i0;
        const float* br = B + k * STR + j0;
        float4 a0 = *(const float4*)ar;
        float4 a1 = *(const float4*)(ar + 4);
        float4 b0 = *(const float4*)br;
        float4 b1 = *(const float4*)(br + 4);
        ull bp0 = pk(b0.x, b0.y), bp1 = pk(b0.z, b0.w);
        ull bp2 = pk(b1.x, b1.y), bp3 = pk(b1.z, b1.w);
        float av[8] = {a0.x, a0.y, a0.z, a0.w, a1.x, a1.y, a1.z, a1.w};
        #pragma unroll
        for (int r = 0; r < 8; r++) {
            ull ad = pk(av[r], av[r]);
            fma2(acc[r * 4 + 0], ad, bp0);
            fma2(acc[r * 4 + 1], ad, bp1);
            fma2(acc[r * 4 + 2], ad, bp2);
            fma2(acc[r * 4 + 3], ad, bp3);
        }
    }
}

// ---------------------------------------------------------------------------
// Main fused kernel: one CTA per (batch, 128-token block). 256 threads.
// Thread (tx = tid&15, ty = tid>>4) owns rows i0 = ty*8.., cols j0 = tx*8..
// Buffers (all k-major [k][row], stride STR):
//   BUF0 = X^T[d][i]      BUF1 = M[d][j] -> T^T[j][i] -> P^T[u][i]
//   BUF2 = N[d][j] -> U[u][d]
// ---------------------------------------------------------------------------
__global__ void __launch_bounds__(256, 1)
attn_kernel(const float* __restrict__ x, const float* __restrict__ gamma,
            const float* __restrict__ beta, float* __restrict__ out) {
    extern __shared__ float sm[];
    float* sX = sm;                    // BUF0
    float* sW = sm + 128 * STR;        // BUF1
    float* sV = sm + 2 * 128 * STR;    // BUF2

    const int tid = threadIdx.x;
    const int tx = tid & 15, ty = tid >> 4;
    const int i0 = ty * 8, j0 = tx * 8;
    const int blk = blockIdx.x;
    const int b = blk >> 6, n = blk & 63;

    // ---- stage X^T, M, N ----
    {
        const float4* Xg4 = (const float4*)(x + (b * SEQ + n * WIN) * D);
        const float4* M4 = (const float4*)g_M;
        const float4* N4 = (const float4*)g_N;
        #pragma unroll 4
        for (int i = tid; i < 4096; i += 256) {
            int r = i >> 5;            // row (token for X, k for W)
            int c4 = (i & 31) * 4;     // feature base
            float4 v = Xg4[i];
            sX[(c4 + 0) * STR + r] = v.x;
            sX[(c4 + 1) * STR + r] = v.y;
            sX[(c4 + 2) * STR + r] = v.z;
            sX[(c4 + 3) * STR + r] = v.w;
            *(float4*)&sW[r * STR + c4] = M4[i];
            *(float4*)&sV[r * STR + c4] = N4[i];
        }
    }
    __syncthreads();

    ull acc[32];

    // ---- G1: T^T[j][i] = sum_d M[d][j] * X^T[d][i]   (scale folded in M) ----
    gemm8x8(sW, sX, i0, j0, acc);      // rows=j (i0 indexes j), cols=i
    __syncthreads();                   // all G1 reads of sW done
    #pragma unroll
    for (int r = 0; r < 8; r++) {
        float v0, v1, v2, v3, v4, v5, v6, v7;
        upk(acc[r * 4 + 0], v0, v1);
        upk(acc[r * 4 + 1], v2, v3);
        upk(acc[r * 4 + 2], v4, v5);
        upk(acc[r * 4 + 3], v6, v7);
        *(float4*)&sW[(i0 + r) * STR + j0] = make_float4(v0, v1, v2, v3);
        *(float4*)&sW[(i0 + r) * STR + j0 + 4] = make_float4(v4, v5, v6, v7);
    }
    __syncthreads();

    // ---- G2: S[i][u] = sum_j T^T[j][i] * X^T[j][u] ----
    gemm8x8(sW, sX, i0, j0, acc);      // rows=i, cols=u

    // ---- softmax over u (within 16 tx lanes), result in p[r][c] ----
    float p[8][8];
    #pragma unroll
    for (int r = 0; r < 8; r++) {
        float v[8];
        upk(acc[r * 4 + 0], v[0], v[1]);
        upk(acc[r * 4 + 1], v[2], v[3]);
        upk(acc[r * 4 + 2], v[4], v[5]);
        upk(acc[r * 4 + 3], v[6], v[7]);
        float m = v[0];
        #pragma unroll
        for (int c = 1; c < 8; c++) m = fmaxf(m, v[c]);
        m = rmax16(m);
        float s = 0.f;
        #pragma unroll
        for (int c = 0; c < 8; c++) {
            v[c] = __expf(v[c] - m);
            s += v[c];
        }
        s = rsum16(s);
        float inv = 1.0f / s;
        #pragma unroll
        for (int c = 0; c < 8; c++) p[r][c] = v[c] * inv;
    }
    __syncthreads();                   // all G2 reads of sW done

    // ---- store P^T[u][i] into BUF1 (scattered; only transposed store left) ----
    #pragma unroll
    for (int c = 0; c < 8; c++) {
        *(float4*)&sW[(j0 + c) * STR + i0] =
            make_float4(p[0][c], p[1][c], p[2][c], p[3][c]);
        *(float4*)&sW[(j0 + c) * STR + i0 + 4] =
            make_float4(p[4][c], p[5][c], p[6][c], p[7][c]);
    }

    // ---- G3: U[u][d] = sum_f X^T[f][u] * N[f][d] ----
    gemm8x8(sX, sV, i0, j0, acc);      // rows=u, cols=d
    __syncthreads();                   // G3 reads of sV done + P^T stores visible
    #pragma unroll
    for (int r = 0; r < 8; r++) {
        float v0, v1, v2, v3, v4, v5, v6, v7;
        upk(acc[r * 4 + 0], v0, v1);
        upk(acc[r * 4 + 1], v2, v3);
        upk(acc[r * 4 + 2], v4, v5);
        upk(acc[r * 4 + 3], v6, v7);
        *(float4*)&sV[(i0 + r) * STR + j0] = make_float4(v0, v1, v2, v3);
        *(float4*)&sV[(i0 + r) * STR + j0 + 4] = make_float4(v4, v5, v6, v7);
    }
    __syncthreads();

    // ---- G4: H[i][d] = sum_u P^T[u][i] * U[u][d] ----
    gemm8x8(sW, sV, i0, j0, acc);      // rows=i, cols=d

    // ---- LayerNorm + exact GELU + store ----
    float4 g0 = *(const float4*)(gamma + j0);
    float4 g1 = *(const float4*)(gamma + j0 + 4);
    float4 b0 = *(const float4*)(beta + j0);
    float4 b1 = *(const float4*)(beta + j0 + 4);
    float gc[8] = {g0.x, g0.y, g0.z, g0.w, g1.x, g1.y, g1.z, g1.w};
    float bc[8] = {b0.x, b0.y, b0.z, b0.w, b1.x, b1.y, b1.z, b1.w};

    float* outp = out + (b * 2 * SEQ + n * WIN) * D;
    #pragma unroll
    for (int r = 0; r < 8; r++) {
        float v[8];
        upk(acc[r * 4 + 0], v[0], v[1]);
        upk(acc[r * 4 + 1], v[2], v[3]);
        upk(acc[r * 4 + 2], v[4], v[5]);
        upk(acc[r * 4 + 3], v[6], v[7]);
        float s = 0.f;
        #pragma unroll
        for (int c = 0; c < 8; c++) s += v[c];
        s = rsum16(s);
        float mu = s * (1.0f / 128.0f);
        float var = 0.f;
        #pragma unroll
        for (int c = 0; c < 8; c++) {
            float dlt = v[c] - mu;
            var += dlt * dlt;
        }
        var = rsum16(var);
        float rstd = rsqrtf(var * (1.0f / 128.0f) + 1e-5f);
        float o[8];
        #pragma unroll
        for (int c = 0; c < 8; c++) {
            float y = (v[c] - mu) * rstd * gc[c] + bc[c];
            o[c] = 0.5f * y * (1.f + erff(y * 0.70710678118654752f));
        }
        *(float4*)&outp[(i0 + r) * D + j0] = make_float4(o[0], o[1], o[2], o[3]);
        *(float4*)&outp[(i0 + r) * D + j0 + 4] =
            make_float4(o[4], o[5], o[6], o[7]);
    }
}

// ---------------------------------------------------------------------------
extern "C" void kernel_launch(void* const* d_in, const int* in_sizes, int n_in,
                              void* d_out, int out_size) {
    const float* x     = (const float*)d_in[0];
    const float* Wq    = (const float*)d_in[1];
    const float* Wk    = (const float*)d_in[2];
    const float* Wv    = (const float*)d_in[3];
    const float* Wo    = (const float*)d_in[4];
    const float* gamma = (const float*)d_in[5];
    const float* beta  = (const float*)d_in[6];
    float* out = (float*)d_out;

    cudaFuncSetAttribute(attn_kernel,
                         cudaFuncAttributeMaxDynamicSharedMemorySize,
                         SMEM_BYTES);

    precompute_kernel<<<128, 128>>>(Wq, Wk, Wv, Wo);
    fill_kernel<<<1024, 256>>>(beta, (float4*)out);
    attn_kernel<<<BATCH * (SEQ / WIN), 256, SMEM_BYTES>>>(x, gamma, beta, out);
}